// round 3
// baseline (speedup 1.0000x reference)
#include <cuda_runtime.h>
#include <math.h>

#define Bn 4
#define Tn 2048
#define Cn 512
#define Hn 8
#define Dn 64
#define NHn (Bn*Hn)          // 32 heads
#define EPSF 1.1920929e-07f

#define BM 128
#define BN 128
#define BK 16
#define PAD 8
#define NT 256

// ---------------- scratch (device globals; no allocation allowed) -------------
__device__ __align__(16) float g_W[Cn * Cn];                        // 1 MB
__device__ __align__(16) float g_w[(size_t)NHn * Tn * Dn];          // 16 MB (B,H,T,D)
__device__ __align__(16) float g_inv[NHn * Tn];                     // rmsnorm inverses
__device__ __align__(16) float g_P[(size_t)NHn * Tn * Tn];          // 512 MB  exp(att)
__device__ __align__(16) float g_rowpart[NHn * Tn * (Tn/BN)];       // 4 MB
__device__ __align__(16) float g_colpart[NHn * Tn * (Tn/BM)];       // 4 MB
__device__ __align__(16) float g_rinv[NHn * Tn];
__device__ __align__(16) float g_cinv[NHn * Tn];
__device__ __align__(16) float g_y[(size_t)Bn * Tn * Cn];           // 16 MB (B,T,C)

// ---------------- K1: W = qkv + delta ----------------
__global__ void k_addw(const float* __restrict__ qkv, const float* __restrict__ dw) {
    int i = blockIdx.x * 256 + threadIdx.x;
    g_W[i] = qkv[i] + dw[i];
}

// ---------------- K2: w = x @ W^T, scattered to (B,H,T,D). 128x128x16 ----------------
__global__ void __launch_bounds__(NT, 2) k_gemm1(const float* __restrict__ x) {
    __shared__ float As[BK][BM + PAD];
    __shared__ float Bs[BK][BN + PAD];
    const int tid = threadIdx.x;
    const int bm = blockIdx.y * BM;
    const int bn = blockIdx.x * BN;
    const int lr = tid >> 1;          // 0..127
    const int lc = (tid & 1) << 3;    // 0 or 8
    const int tx = tid & 15, ty = tid >> 4;
    float acc[8][8] = {};
    for (int k0 = 0; k0 < Cn; k0 += BK) {
        float4 a0 = *(const float4*)&x[(size_t)(bm + lr) * Cn + k0 + lc];
        float4 a1 = *(const float4*)&x[(size_t)(bm + lr) * Cn + k0 + lc + 4];
        As[lc + 0][lr] = a0.x; As[lc + 1][lr] = a0.y; As[lc + 2][lr] = a0.z; As[lc + 3][lr] = a0.w;
        As[lc + 4][lr] = a1.x; As[lc + 5][lr] = a1.y; As[lc + 6][lr] = a1.z; As[lc + 7][lr] = a1.w;
        float4 b0 = *(const float4*)&g_W[(size_t)(bn + lr) * Cn + k0 + lc];
        float4 b1 = *(const float4*)&g_W[(size_t)(bn + lr) * Cn + k0 + lc + 4];
        Bs[lc + 0][lr] = b0.x; Bs[lc + 1][lr] = b0.y; Bs[lc + 2][lr] = b0.z; Bs[lc + 3][lr] = b0.w;
        Bs[lc + 4][lr] = b1.x; Bs[lc + 5][lr] = b1.y; Bs[lc + 6][lr] = b1.z; Bs[lc + 7][lr] = b1.w;
        __syncthreads();
        #pragma unroll
        for (int k = 0; k < BK; k++) {
            float4 av0 = *(float4*)&As[k][ty * 8];
            float4 av1 = *(float4*)&As[k][ty * 8 + 4];
            float4 bv0 = *(float4*)&Bs[k][tx * 8];
            float4 bv1 = *(float4*)&Bs[k][tx * 8 + 4];
            float a[8] = {av0.x, av0.y, av0.z, av0.w, av1.x, av1.y, av1.z, av1.w};
            float b[8] = {bv0.x, bv0.y, bv0.z, bv0.w, bv1.x, bv1.y, bv1.z, bv1.w};
            #pragma unroll
            for (int i = 0; i < 8; i++)
                #pragma unroll
                for (int j = 0; j < 8; j++) acc[i][j] += a[i] * b[j];
        }
        __syncthreads();
    }
    #pragma unroll
    for (int i = 0; i < 8; i++) {
        int m = bm + ty * 8 + i;
        int b = m >> 11, t = m & (Tn - 1);
        #pragma unroll
        for (int j = 0; j < 8; j += 4) {
            int n = bn + tx * 8 + j;
            int h = n >> 6, d = n & 63;
            *(float4*)&g_w[(((size_t)(b * Hn + h)) * Tn + t) * Dn + d] =
                make_float4(acc[i][j], acc[i][j + 1], acc[i][j + 2], acc[i][j + 3]);
        }
    }
}

// ---------------- K3: per-row rmsnorm inverse ----------------
__global__ void k_inv() {
    int row = blockIdx.x * 8 + (threadIdx.x >> 5);
    int lane = threadIdx.x & 31;
    const float* wr = g_w + (size_t)row * Dn;
    float v0 = wr[lane], v1 = wr[lane + 32];
    float s = v0 * v0 + v1 * v1;
    #pragma unroll
    for (int o = 16; o; o >>= 1) s += __shfl_xor_sync(0xFFFFFFFFu, s, o);
    if (lane == 0) g_inv[row] = rsqrtf(s * (1.0f / Dn) + EPSF);
}

// ---------------- K4: P = exp(rms(w,g1) @ rms(w,g2)^T / 8), with partial row/col sums
// Valid because rmsnorm rows have L2 norm <= sqrt(D)=8 so |att| <= 8 (no overflow).
__global__ void __launch_bounds__(NT, 2) k_att(const float* __restrict__ g1,
                                               const float* __restrict__ g2) {
    __shared__ float As[BK][BM + PAD];
    __shared__ float Bs[BK][BN + PAD];
    const int head = blockIdx.z;
    const float* wh = g_w + (size_t)head * Tn * Dn;
    const float* invh = g_inv + head * Tn;
    float* Ph = g_P + (size_t)head * Tn * Tn;
    const int tid = threadIdx.x;
    const int bi = blockIdx.y * BM;
    const int bj = blockIdx.x * BN;
    const int lr = tid >> 1;
    const int lc = (tid & 1) << 3;
    const int tx = tid & 15, ty = tid >> 4;
    const float ainv = invh[bi + lr];
    const float binv = invh[bj + lr];
    float acc[8][8] = {};
    for (int k0 = 0; k0 < Dn; k0 += BK) {
        float4 a0 = *(const float4*)&wh[(size_t)(bi + lr) * Dn + k0 + lc];
        float4 a1 = *(const float4*)&wh[(size_t)(bi + lr) * Dn + k0 + lc + 4];
        float4 q0 = *(const float4*)&g1[k0 + lc];
        float4 q1 = *(const float4*)&g1[k0 + lc + 4];
        As[lc + 0][lr] = a0.x * q0.x * ainv; As[lc + 1][lr] = a0.y * q0.y * ainv;
        As[lc + 2][lr] = a0.z * q0.z * ainv; As[lc + 3][lr] = a0.w * q0.w * ainv;
        As[lc + 4][lr] = a1.x * q1.x * ainv; As[lc + 5][lr] = a1.y * q1.y * ainv;
        As[lc + 6][lr] = a1.z * q1.z * ainv; As[lc + 7][lr] = a1.w * q1.w * ainv;
        float4 b0 = *(const float4*)&wh[(size_t)(bj + lr) * Dn + k0 + lc];
        float4 b1 = *(const float4*)&wh[(size_t)(bj + lr) * Dn + k0 + lc + 4];
        float4 r0 = *(const float4*)&g2[k0 + lc];
        float4 r1 = *(const float4*)&g2[k0 + lc + 4];
        Bs[lc + 0][lr] = b0.x * r0.x * binv; Bs[lc + 1][lr] = b0.y * r0.y * binv;
        Bs[lc + 2][lr] = b0.z * r0.z * binv; Bs[lc + 3][lr] = b0.w * r0.w * binv;
        Bs[lc + 4][lr] = b1.x * r1.x * binv; Bs[lc + 5][lr] = b1.y * r1.y * binv;
        Bs[lc + 6][lr] = b1.z * r1.z * binv; Bs[lc + 7][lr] = b1.w * r1.w * binv;
        __syncthreads();
        #pragma unroll
        for (int k = 0; k < BK; k++) {
            float4 av0 = *(float4*)&As[k][ty * 8];
            float4 av1 = *(float4*)&As[k][ty * 8 + 4];
            float4 bv0 = *(float4*)&Bs[k][tx * 8];
            float4 bv1 = *(float4*)&Bs[k][tx * 8 + 4];
            float a[8] = {av0.x, av0.y, av0.z, av0.w, av1.x, av1.y, av1.z, av1.w};
            float b[8] = {bv0.x, bv0.y, bv0.z, bv0.w, bv1.x, bv1.y, bv1.z, bv1.w};
            #pragma unroll
            for (int i = 0; i < 8; i++)
                #pragma unroll
                for (int j = 0; j < 8; j++) acc[i][j] += a[i] * b[j];
        }
        __syncthreads();
    }
    // epilogue: exp + store P + deterministic per-block partial row/col sums
    float rsum[8] = {}, csum[8] = {};
    #pragma unroll
    for (int i = 0; i < 8; i++) {
        #pragma unroll
        for (int j = 0; j < 8; j++) {
            float e = __expf(acc[i][j] * 0.125f);
            acc[i][j] = e;
            rsum[i] += e;
            csum[j] += e;
        }
        *(float4*)&Ph[(size_t)(bi + ty * 8 + i) * Tn + bj + tx * 8] =
            make_float4(acc[i][0], acc[i][1], acc[i][2], acc[i][3]);
        *(float4*)&Ph[(size_t)(bi + ty * 8 + i) * Tn + bj + tx * 8 + 4] =
            make_float4(acc[i][4], acc[i][5], acc[i][6], acc[i][7]);
    }
    float* red = &As[0][0];   // reuse smem: need 128*16 = 2048 floats (<= 16*136)
    __syncthreads();
    #pragma unroll
    for (int i = 0; i < 8; i++) red[(ty * 8 + i) * 16 + tx] = rsum[i];
    __syncthreads();
    if (tid < 128) {
        float s = 0;
        #pragma unroll
        for (int t = 0; t < 16; t++) s += red[tid * 16 + t];
        g_rowpart[((size_t)head * Tn + bi + tid) * (Tn / BN) + blockIdx.x] = s;
    }
    __syncthreads();
    #pragma unroll
    for (int j = 0; j < 8; j++) red[(tx * 8 + j) * 16 + ty] = csum[j];
    __syncthreads();
    if (tid < 128) {
        float s = 0;
        #pragma unroll
        for (int t = 0; t < 16; t++) s += red[tid * 16 + t];
        g_colpart[((size_t)head * Tn + bj + tid) * (Tn / BM) + blockIdx.y] = s;
    }
}

// ---------------- K5: reduce partials -> 1/rowsum, 1/colsum ----------------
__global__ void k_red() {
    int r = blockIdx.x * 256 + threadIdx.x;   // over NH*T = 65536
    float s = 0, c = 0;
    #pragma unroll
    for (int t = 0; t < 16; t++) {
        s += g_rowpart[(size_t)r * 16 + t];
        c += g_colpart[(size_t)r * 16 + t];
    }
    g_rinv[r] = 1.0f / s;
    g_cinv[r] = 1.0f / c;
}

// ---------------- K6: y = [P*(rinv_i + cinv_j)] @ rms(w,g3) -> (B,T,C) ----------------
// 128x64x16 tiles, 8x4 microtile.
__global__ void __launch_bounds__(NT, 2) k_y(const float* __restrict__ g3) {
    __shared__ float As[BK][BM + PAD];
    __shared__ float Bs[BK][Dn];
    const int head = blockIdx.y;
    const int b = head / Hn, h = head % Hn;
    const float* Ph = g_P + (size_t)head * Tn * Tn;
    const float* wh = g_w + (size_t)head * Tn * Dn;
    const float* invh = g_inv + head * Tn;
    const float* rinvh = g_rinv + head * Tn;
    const float* cinvh = g_cinv + head * Tn;
    const int bi = blockIdx.x * BM;
    const int tid = threadIdx.x;
    const int lr = tid >> 1;
    const int lc = (tid & 1) << 3;
    const int bk = tid >> 4;          // 0..15
    const int bn4 = (tid & 15) << 2;  // 0..60
    const int tx = tid & 15, ty = tid >> 4;
    const float scaleR = rinvh[bi + lr];
    const float4 g3v = *(const float4*)&g3[bn4];
    float acc[8][4] = {};
    for (int k0 = 0; k0 < Tn; k0 += BK) {
        float4 p0 = *(const float4*)&Ph[(size_t)(bi + lr) * Tn + k0 + lc];
        float4 p1 = *(const float4*)&Ph[(size_t)(bi + lr) * Tn + k0 + lc + 4];
        float4 c0 = *(const float4*)&cinvh[k0 + lc];
        float4 c1 = *(const float4*)&cinvh[k0 + lc + 4];
        As[lc + 0][lr] = p0.x * (scaleR + c0.x); As[lc + 1][lr] = p0.y * (scaleR + c0.y);
        As[lc + 2][lr] = p0.z * (scaleR + c0.z); As[lc + 3][lr] = p0.w * (scaleR + c0.w);
        As[lc + 4][lr] = p1.x * (scaleR + c1.x); As[lc + 5][lr] = p1.y * (scaleR + c1.y);
        As[lc + 6][lr] = p1.z * (scaleR + c1.z); As[lc + 7][lr] = p1.w * (scaleR + c1.w);
        float vinv = invh[k0 + bk];
        float4 v = *(const float4*)&wh[(size_t)(k0 + bk) * Dn + bn4];
        *(float4*)&Bs[bk][bn4] = make_float4(v.x * g3v.x * vinv, v.y * g3v.y * vinv,
                                             v.z * g3v.z * vinv, v.w * g3v.w * vinv);
        __syncthreads();
        #pragma unroll
        for (int k = 0; k < BK; k++) {
            float4 av0 = *(float4*)&As[k][ty * 8];
            float4 av1 = *(float4*)&As[k][ty * 8 + 4];
            float4 bv = *(float4*)&Bs[k][tx * 4];
            float a[8] = {av0.x, av0.y, av0.z, av0.w, av1.x, av1.y, av1.z, av1.w};
            float bb[4] = {bv.x, bv.y, bv.z, bv.w};
            #pragma unroll
            for (int i = 0; i < 8; i++)
                #pragma unroll
                for (int j = 0; j < 4; j++) acc[i][j] += a[i] * bb[j];
        }
        __syncthreads();
    }
    #pragma unroll
    for (int i = 0; i < 8; i++) {
        int t = bi + ty * 8 + i;
        *(float4*)&g_y[((size_t)b * Tn + t) * Cn + h * Dn + tx * 4] =
            make_float4(acc[i][0], acc[i][1], acc[i][2], acc[i][3]);
    }
}

// ---------------- K7: out = y @ W. 128x128x16 ----------------
__global__ void __launch_bounds__(NT, 2) k_out(float* __restrict__ out) {
    __shared__ float As[BK][BM + PAD];
    __shared__ float Bs[BK][BN + PAD];
    const int tid = threadIdx.x;
    const int bm = blockIdx.y * BM;
    const int bn = blockIdx.x * BN;
    const int lr = tid >> 1;
    const int lc = (tid & 1) << 3;
    const int bk = tid >> 4;          // 0..15
    const int bn8 = (tid & 15) << 3;  // 0..120
    const int tx = tid & 15, ty = tid >> 4;
    float acc[8][8] = {};
    for (int k0 = 0; k0 < Cn; k0 += BK) {
        float4 a0 = *(const float4*)&g_y[(size_t)(bm + lr) * Cn + k0 + lc];
        float4 a1 = *(const float4*)&g_y[(size_t)(bm + lr) * Cn + k0 + lc + 4];
        As[lc + 0][lr] = a0.x; As[lc + 1][lr] = a0.y; As[lc + 2][lr] = a0.z; As[lc + 3][lr] = a0.w;
        As[lc + 4][lr] = a1.x; As[lc + 5][lr] = a1.y; As[lc + 6][lr] = a1.z; As[lc + 7][lr] = a1.w;
        *(float4*)&Bs[bk][bn8]     = *(const float4*)&g_W[(size_t)(k0 + bk) * Cn + bn + bn8];
        *(float4*)&Bs[bk][bn8 + 4] = *(const float4*)&g_W[(size_t)(k0 + bk) * Cn + bn + bn8 + 4];
        __syncthreads();
        #pragma unroll
        for (int k = 0; k < BK; k++) {
            float4 av0 = *(float4*)&As[k][ty * 8];
            float4 av1 = *(float4*)&As[k][ty * 8 + 4];
            float4 bv0 = *(float4*)&Bs[k][tx * 8];
            float4 bv1 = *(float4*)&Bs[k][tx * 8 + 4];
            float a[8] = {av0.x, av0.y, av0.z, av0.w, av1.x, av1.y, av1.z, av1.w};
            float b[8] = {bv0.x, bv0.y, bv0.z, bv0.w, bv1.x, bv1.y, bv1.z, bv1.w};
            #pragma unroll
            for (int i = 0; i < 8; i++)
                #pragma unroll
                for (int j = 0; j < 8; j++) acc[i][j] += a[i] * b[j];
        }
        __syncthreads();
    }
    #pragma unroll
    for (int i = 0; i < 8; i++) {
        #pragma unroll
        for (int j = 0; j < 8; j += 4)
            *(float4*)&out[(size_t)(bm + ty * 8 + i) * Cn + bn + tx * 8 + j] =
                make_float4(acc[i][j], acc[i][j + 1], acc[i][j + 2], acc[i][j + 3]);
    }
}

// ---------------- launcher ----------------
extern "C" void kernel_launch(void* const* d_in, const int* in_sizes, int n_in,
                              void* d_out, int out_size) {
    const float* x   = (const float*)d_in[0];
    const float* dw  = (const float*)d_in[1];
    const float* qkv = (const float*)d_in[2];
    const float* g1  = (const float*)d_in[3];
    const float* g2  = (const float*)d_in[4];
    const float* g3  = (const float*)d_in[5];
    float* out = (float*)d_out;

    k_addw<<<(Cn * Cn) / 256, 256>>>(qkv, dw);
    k_gemm1<<<dim3(Cn / BN, (Bn * Tn) / BM), NT>>>(x);
    k_inv<<<(NHn * Tn) / 8, 256>>>();
    k_att<<<dim3(Tn / BN, Tn / BM, NHn), NT>>>(g1, g2);
    k_red<<<(NHn * Tn) / 256, 256>>>();
    k_y<<<dim3(Tn / BM, NHn), NT>>>(g3);
    k_out<<<dim3(Cn / BN, (Bn * Tn) / BM), NT>>>(out);
}

// round 4
// speedup vs baseline: 1.0014x; 1.0014x over previous
#include <cuda_runtime.h>
#include <math.h>

#define Bn 4
#define Tn 2048
#define Cn 512
#define Hn 8
#define Dn 64
#define NHn (Bn*Hn)          // 32 heads
#define EPSF 1.1920929e-07f

#define BM 128
#define BN 128
#define BK 16
#define PAD 8
#define NT 256

// ---------------- scratch (device globals; no allocation allowed) -------------
__device__ __align__(16) float g_W[Cn * Cn];                        // 1 MB
__device__ __align__(16) float g_w[(size_t)NHn * Tn * Dn];          // 16 MB (B,H,T,D)
__device__ __align__(16) float g_inv[NHn * Tn];                     // rmsnorm inverses
__device__ __align__(16) float g_P[(size_t)NHn * Tn * Tn];          // 512 MB  exp(att)
__device__ __align__(16) float g_rowpart[NHn * Tn * (Tn/BN)];       // 4 MB
__device__ __align__(16) float g_colpart[NHn * Tn * (Tn/BM)];       // 4 MB
__device__ __align__(16) float g_rinv[NHn * Tn];
__device__ __align__(16) float g_cinv[NHn * Tn];
__device__ __align__(16) float g_y[(size_t)Bn * Tn * Cn];           // 16 MB (B,T,C)

// ---------------- K1: W = qkv + delta ----------------
__global__ void k_addw(const float* __restrict__ qkv, const float* __restrict__ dw) {
    int i = blockIdx.x * 256 + threadIdx.x;
    g_W[i] = qkv[i] + dw[i];
}

// ---------------- K2: w = x @ W^T, scattered to (B,H,T,D). 128x128x16 ----------------
__global__ void __launch_bounds__(NT, 2) k_gemm1(const float* __restrict__ x) {
    __shared__ float As[BK][BM + PAD];
    __shared__ float Bs[BK][BN + PAD];
    const int tid = threadIdx.x;
    const int bm = blockIdx.y * BM;
    const int bn = blockIdx.x * BN;
    const int lr = tid >> 1;          // 0..127
    const int lc = (tid & 1) << 3;    // 0 or 8
    const int tx = tid & 15, ty = tid >> 4;
    float acc[8][8] = {};
    for (int k0 = 0; k0 < Cn; k0 += BK) {
        float4 a0 = *(const float4*)&x[(size_t)(bm + lr) * Cn + k0 + lc];
        float4 a1 = *(const float4*)&x[(size_t)(bm + lr) * Cn + k0 + lc + 4];
        As[lc + 0][lr] = a0.x; As[lc + 1][lr] = a0.y; As[lc + 2][lr] = a0.z; As[lc + 3][lr] = a0.w;
        As[lc + 4][lr] = a1.x; As[lc + 5][lr] = a1.y; As[lc + 6][lr] = a1.z; As[lc + 7][lr] = a1.w;
        float4 b0 = *(const float4*)&g_W[(size_t)(bn + lr) * Cn + k0 + lc];
        float4 b1 = *(const float4*)&g_W[(size_t)(bn + lr) * Cn + k0 + lc + 4];
        Bs[lc + 0][lr] = b0.x; Bs[lc + 1][lr] = b0.y; Bs[lc + 2][lr] = b0.z; Bs[lc + 3][lr] = b0.w;
        Bs[lc + 4][lr] = b1.x; Bs[lc + 5][lr] = b1.y; Bs[lc + 6][lr] = b1.z; Bs[lc + 7][lr] = b1.w;
        __syncthreads();
        #pragma unroll
        for (int k = 0; k < BK; k++) {
            float4 av0 = *(float4*)&As[k][ty * 8];
            float4 av1 = *(float4*)&As[k][ty * 8 + 4];
            float4 bv0 = *(float4*)&Bs[k][tx * 8];
            float4 bv1 = *(float4*)&Bs[k][tx * 8 + 4];
            float a[8] = {av0.x, av0.y, av0.z, av0.w, av1.x, av1.y, av1.z, av1.w};
            float b[8] = {bv0.x, bv0.y, bv0.z, bv0.w, bv1.x, bv1.y, bv1.z, bv1.w};
            #pragma unroll
            for (int i = 0; i < 8; i++)
                #pragma unroll
                for (int j = 0; j < 8; j++) acc[i][j] += a[i] * b[j];
        }
        __syncthreads();
    }
    #pragma unroll
    for (int i = 0; i < 8; i++) {
        int m = bm + ty * 8 + i;
        int b = m >> 11, t = m & (Tn - 1);
        #pragma unroll
        for (int j = 0; j < 8; j += 4) {
            int n = bn + tx * 8 + j;
            int h = n >> 6, d = n & 63;
            *(float4*)&g_w[(((size_t)(b * Hn + h)) * Tn + t) * Dn + d] =
                make_float4(acc[i][j], acc[i][j + 1], acc[i][j + 2], acc[i][j + 3]);
        }
    }
}

// ---------------- K3: per-row rmsnorm inverse ----------------
__global__ void k_inv() {
    int row = blockIdx.x * 8 + (threadIdx.x >> 5);
    int lane = threadIdx.x & 31;
    const float* wr = g_w + (size_t)row * Dn;
    float v0 = wr[lane], v1 = wr[lane + 32];
    float s = v0 * v0 + v1 * v1;
    #pragma unroll
    for (int o = 16; o; o >>= 1) s += __shfl_xor_sync(0xFFFFFFFFu, s, o);
    if (lane == 0) g_inv[row] = rsqrtf(s * (1.0f / Dn) + EPSF);
}

// ---------------- K4: P = exp(rms(w,g1) @ rms(w,g2)^T / 8), with partial row/col sums
// Valid because rmsnorm rows have L2 norm <= sqrt(D)=8 so |att| <= 8 (no overflow).
__global__ void __launch_bounds__(NT, 2) k_att(const float* __restrict__ g1,
                                               const float* __restrict__ g2) {
    __shared__ float As[BK][BM + PAD];
    __shared__ float Bs[BK][BN + PAD];
    const int head = blockIdx.z;
    const float* wh = g_w + (size_t)head * Tn * Dn;
    const float* invh = g_inv + head * Tn;
    float* Ph = g_P + (size_t)head * Tn * Tn;
    const int tid = threadIdx.x;
    const int bi = blockIdx.y * BM;
    const int bj = blockIdx.x * BN;
    const int lr = tid >> 1;
    const int lc = (tid & 1) << 3;
    const int tx = tid & 15, ty = tid >> 4;
    const float ainv = invh[bi + lr];
    const float binv = invh[bj + lr];
    float acc[8][8] = {};
    for (int k0 = 0; k0 < Dn; k0 += BK) {
        float4 a0 = *(const float4*)&wh[(size_t)(bi + lr) * Dn + k0 + lc];
        float4 a1 = *(const float4*)&wh[(size_t)(bi + lr) * Dn + k0 + lc + 4];
        float4 q0 = *(const float4*)&g1[k0 + lc];
        float4 q1 = *(const float4*)&g1[k0 + lc + 4];
        As[lc + 0][lr] = a0.x * q0.x * ainv; As[lc + 1][lr] = a0.y * q0.y * ainv;
        As[lc + 2][lr] = a0.z * q0.z * ainv; As[lc + 3][lr] = a0.w * q0.w * ainv;
        As[lc + 4][lr] = a1.x * q1.x * ainv; As[lc + 5][lr] = a1.y * q1.y * ainv;
        As[lc + 6][lr] = a1.z * q1.z * ainv; As[lc + 7][lr] = a1.w * q1.w * ainv;
        float4 b0 = *(const float4*)&wh[(size_t)(bj + lr) * Dn + k0 + lc];
        float4 b1 = *(const float4*)&wh[(size_t)(bj + lr) * Dn + k0 + lc + 4];
        float4 r0 = *(const float4*)&g2[k0 + lc];
        float4 r1 = *(const float4*)&g2[k0 + lc + 4];
        Bs[lc + 0][lr] = b0.x * r0.x * binv; Bs[lc + 1][lr] = b0.y * r0.y * binv;
        Bs[lc + 2][lr] = b0.z * r0.z * binv; Bs[lc + 3][lr] = b0.w * r0.w * binv;
        Bs[lc + 4][lr] = b1.x * r1.x * binv; Bs[lc + 5][lr] = b1.y * r1.y * binv;
        Bs[lc + 6][lr] = b1.z * r1.z * binv; Bs[lc + 7][lr] = b1.w * r1.w * binv;
        __syncthreads();
        #pragma unroll
        for (int k = 0; k < BK; k++) {
            float4 av0 = *(float4*)&As[k][ty * 8];
            float4 av1 = *(float4*)&As[k][ty * 8 + 4];
            float4 bv0 = *(float4*)&Bs[k][tx * 8];
            float4 bv1 = *(float4*)&Bs[k][tx * 8 + 4];
            float a[8] = {av0.x, av0.y, av0.z, av0.w, av1.x, av1.y, av1.z, av1.w};
            float b[8] = {bv0.x, bv0.y, bv0.z, bv0.w, bv1.x, bv1.y, bv1.z, bv1.w};
            #pragma unroll
            for (int i = 0; i < 8; i++)
                #pragma unroll
                for (int j = 0; j < 8; j++) acc[i][j] += a[i] * b[j];
        }
        __syncthreads();
    }
    // epilogue: exp + store P + deterministic per-block partial row/col sums
    float rsum[8] = {}, csum[8] = {};
    #pragma unroll
    for (int i = 0; i < 8; i++) {
        #pragma unroll
        for (int j = 0; j < 8; j++) {
            float e = __expf(acc[i][j] * 0.125f);
            acc[i][j] = e;
            rsum[i] += e;
            csum[j] += e;
        }
        *(float4*)&Ph[(size_t)(bi + ty * 8 + i) * Tn + bj + tx * 8] =
            make_float4(acc[i][0], acc[i][1], acc[i][2], acc[i][3]);
        *(float4*)&Ph[(size_t)(bi + ty * 8 + i) * Tn + bj + tx * 8 + 4] =
            make_float4(acc[i][4], acc[i][5], acc[i][6], acc[i][7]);
    }
    float* red = &As[0][0];   // reuse smem: need 128*16 = 2048 floats (<= 16*136)
    __syncthreads();
    #pragma unroll
    for (int i = 0; i < 8; i++) red[(ty * 8 + i) * 16 + tx] = rsum[i];
    __syncthreads();
    if (tid < 128) {
        float s = 0;
        #pragma unroll
        for (int t = 0; t < 16; t++) s += red[tid * 16 + t];
        g_rowpart[((size_t)head * Tn + bi + tid) * (Tn / BN) + blockIdx.x] = s;
    }
    __syncthreads();
    #pragma unroll
    for (int j = 0; j < 8; j++) red[(tx * 8 + j) * 16 + ty] = csum[j];
    __syncthreads();
    if (tid < 128) {
        float s = 0;
        #pragma unroll
        for (int t = 0; t < 16; t++) s += red[tid * 16 + t];
        g_colpart[((size_t)head * Tn + bj + tid) * (Tn / BM) + blockIdx.y] = s;
    }
}

// ---------------- K5: reduce partials -> 1/rowsum, 1/colsum ----------------
__global__ void k_red() {
    int r = blockIdx.x * 256 + threadIdx.x;   // over NH*T = 65536
    float s = 0, c = 0;
    #pragma unroll
    for (int t = 0; t < 16; t++) {
        s += g_rowpart[(size_t)r * 16 + t];
        c += g_colpart[(size_t)r * 16 + t];
    }
    g_rinv[r] = 1.0f / s;
    g_cinv[r] = 1.0f / c;
}

// ---------------- K6: y = [P*(rinv_i + cinv_j)] @ rms(w,g3) -> (B,T,C) ----------------
// 128x64x16 tiles, 8x4 microtile.
__global__ void __launch_bounds__(NT, 2) k_y(const float* __restrict__ g3) {
    __shared__ float As[BK][BM + PAD];
    __shared__ float Bs[BK][Dn];
    const int head = blockIdx.y;
    const int b = head / Hn, h = head % Hn;
    const float* Ph = g_P + (size_t)head * Tn * Tn;
    const float* wh = g_w + (size_t)head * Tn * Dn;
    const float* invh = g_inv + head * Tn;
    const float* rinvh = g_rinv + head * Tn;
    const float* cinvh = g_cinv + head * Tn;
    const int bi = blockIdx.x * BM;
    const int tid = threadIdx.x;
    const int lr = tid >> 1;
    const int lc = (tid & 1) << 3;
    const int bk = tid >> 4;          // 0..15
    const int bn4 = (tid & 15) << 2;  // 0..60
    const int tx = tid & 15, ty = tid >> 4;
    const float scaleR = rinvh[bi + lr];
    const float4 g3v = *(const float4*)&g3[bn4];
    float acc[8][4] = {};
    for (int k0 = 0; k0 < Tn; k0 += BK) {
        float4 p0 = *(const float4*)&Ph[(size_t)(bi + lr) * Tn + k0 + lc];
        float4 p1 = *(const float4*)&Ph[(size_t)(bi + lr) * Tn + k0 + lc + 4];
        float4 c0 = *(const float4*)&cinvh[k0 + lc];
        float4 c1 = *(const float4*)&cinvh[k0 + lc + 4];
        As[lc + 0][lr] = p0.x * (scaleR + c0.x); As[lc + 1][lr] = p0.y * (scaleR + c0.y);
        As[lc + 2][lr] = p0.z * (scaleR + c0.z); As[lc + 3][lr] = p0.w * (scaleR + c0.w);
        As[lc + 4][lr] = p1.x * (scaleR + c1.x); As[lc + 5][lr] = p1.y * (scaleR + c1.y);
        As[lc + 6][lr] = p1.z * (scaleR + c1.z); As[lc + 7][lr] = p1.w * (scaleR + c1.w);
        float vinv = invh[k0 + bk];
        float4 v = *(const float4*)&wh[(size_t)(k0 + bk) * Dn + bn4];
        *(float4*)&Bs[bk][bn4] = make_float4(v.x * g3v.x * vinv, v.y * g3v.y * vinv,
                                             v.z * g3v.z * vinv, v.w * g3v.w * vinv);
        __syncthreads();
        #pragma unroll
        for (int k = 0; k < BK; k++) {
            float4 av0 = *(float4*)&As[k][ty * 8];
            float4 av1 = *(float4*)&As[k][ty * 8 + 4];
            float4 bv = *(float4*)&Bs[k][tx * 4];
            float a[8] = {av0.x, av0.y, av0.z, av0.w, av1.x, av1.y, av1.z, av1.w};
            float bb[4] = {bv.x, bv.y, bv.z, bv.w};
            #pragma unroll
            for (int i = 0; i < 8; i++)
                #pragma unroll
                for (int j = 0; j < 4; j++) acc[i][j] += a[i] * bb[j];
        }
        __syncthreads();
    }
    #pragma unroll
    for (int i = 0; i < 8; i++) {
        int t = bi + ty * 8 + i;
        *(float4*)&g_y[((size_t)b * Tn + t) * Cn + h * Dn + tx * 4] =
            make_float4(acc[i][0], acc[i][1], acc[i][2], acc[i][3]);
    }
}

// ---------------- K7: out = y @ W. 128x128x16 ----------------
__global__ void __launch_bounds__(NT, 2) k_out(float* __restrict__ out) {
    __shared__ float As[BK][BM + PAD];
    __shared__ float Bs[BK][BN + PAD];
    const int tid = threadIdx.x;
    const int bm = blockIdx.y * BM;
    const int bn = blockIdx.x * BN;
    const int lr = tid >> 1;
    const int lc = (tid & 1) << 3;
    const int bk = tid >> 4;          // 0..15
    const int bn8 = (tid & 15) << 3;  // 0..120
    const int tx = tid & 15, ty = tid >> 4;
    float acc[8][8] = {};
    for (int k0 = 0; k0 < Cn; k0 += BK) {
        float4 a0 = *(const float4*)&g_y[(size_t)(bm + lr) * Cn + k0 + lc];
        float4 a1 = *(const float4*)&g_y[(size_t)(bm + lr) * Cn + k0 + lc + 4];
        As[lc + 0][lr] = a0.x; As[lc + 1][lr] = a0.y; As[lc + 2][lr] = a0.z; As[lc + 3][lr] = a0.w;
        As[lc + 4][lr] = a1.x; As[lc + 5][lr] = a1.y; As[lc + 6][lr] = a1.z; As[lc + 7][lr] = a1.w;
        *(float4*)&Bs[bk][bn8]     = *(const float4*)&g_W[(size_t)(k0 + bk) * Cn + bn + bn8];
        *(float4*)&Bs[bk][bn8 + 4] = *(const float4*)&g_W[(size_t)(k0 + bk) * Cn + bn + bn8 + 4];
        __syncthreads();
        #pragma unroll
        for (int k = 0; k < BK; k++) {
            float4 av0 = *(float4*)&As[k][ty * 8];
            float4 av1 = *(float4*)&As[k][ty * 8 + 4];
            float4 bv0 = *(float4*)&Bs[k][tx * 8];
            float4 bv1 = *(float4*)&Bs[k][tx * 8 + 4];
            float a[8] = {av0.x, av0.y, av0.z, av0.w, av1.x, av1.y, av1.z, av1.w};
            float b[8] = {bv0.x, bv0.y, bv0.z, bv0.w, bv1.x, bv1.y, bv1.z, bv1.w};
            #pragma unroll
            for (int i = 0; i < 8; i++)
                #pragma unroll
                for (int j = 0; j < 8; j++) acc[i][j] += a[i] * b[j];
        }
        __syncthreads();
    }
    #pragma unroll
    for (int i = 0; i < 8; i++) {
        #pragma unroll
        for (int j = 0; j < 8; j += 4)
            *(float4*)&out[(size_t)(bm + ty * 8 + i) * Cn + bn + tx * 8 + j] =
                make_float4(acc[i][j], acc[i][j + 1], acc[i][j + 2], acc[i][j + 3]);
    }
}

// ---------------- launcher ----------------
extern "C" void kernel_launch(void* const* d_in, const int* in_sizes, int n_in,
                              void* d_out, int out_size) {
    const float* x   = (const float*)d_in[0];
    const float* dw  = (const float*)d_in[1];
    const float* qkv = (const float*)d_in[2];
    const float* g1  = (const float*)d_in[3];
    const float* g2  = (const float*)d_in[4];
    const float* g3  = (const float*)d_in[5];
    float* out = (float*)d_out;

    k_addw<<<(Cn * Cn) / 256, 256>>>(qkv, dw);
    k_gemm1<<<dim3(Cn / BN, (Bn * Tn) / BM), NT>>>(x);
    k_inv<<<(NHn * Tn) / 8, 256>>>();
    k_att<<<dim3(Tn / BN, Tn / BM, NHn), NT>>>(g1, g2);
    k_red<<<(NHn * Tn) / 256, 256>>>();
    k_y<<<dim3(Tn / BM, NHn), NT>>>(g3);
    k_out<<<dim3(Cn / BN, (Bn * Tn) / BM), NT>>>(out);
}